// round 8
// baseline (speedup 1.0000x reference)
#include <cuda_runtime.h>

#define MDIM 1024
#define GR   16                 // rows per block = warps per block
#define TPB  512
#define ROWSTRIDE (3*MDIM)      // [x(1024) | pp interleaved(2048)]

// persistent shared layout
#define BUF_BYTES  (GR*ROWSTRIDE*4)            // 196608
#define SIDX_OFF   (BUF_BYTES)                 // short4[M] remapped parents     8192
#define SWT_OFF    (SIDX_OFF + MDIM*8)         // float4[M] (w0',w1',b',-)      16384
#define WEPI_OFF   (SWT_OFF  + MDIM*16)        // float2[M] (wp',wq') permuted   8192
#define EOFF_OFF   (WEPI_OFF + MDIM*8)         // short[1200] epoch offsets      2400
#define SMEM_BYTES (EOFF_OFF + 2400)           // 231776 <= 232448 cap

__device__ __forceinline__ float sigmoid_fold(float t) {   // t = -z*log2e
    float e, p;
    asm("ex2.approx.f32 %0, %1;" : "=f"(e) : "f"(t));
    asm("rcp.approx.f32 %0, %1;" : "=f"(p) : "f"(1.0f + e));
    return p;
}

// ---------------------------------------------------------------------------
// Fused kernel. Setup: level-sort the 1024-step DAG, remap ids to schedule
// order (stores contiguous, plus/prod interleaved as float2), split levels
// into epochs of width <= 32 (no spill path in the main loop). ALL schedule
// tables (incl. permuted epilogue weights) live in per-block smem, consistent
// with this block's own position assignment. Main: one warp per row; body is
// straight-line; next epoch's records are prefetched and turned into final
// LDS/STS addresses before the per-epoch __syncwarp (off the chain).
// ---------------------------------------------------------------------------
__global__ void __launch_bounds__(TPB, 1)
tree_kernel(const float* __restrict__ x,      const int* __restrict__ raw,
            const float* __restrict__ W_base, const float* __restrict__ b_base,
            const float* __restrict__ W_sig,  const float* __restrict__ b_sig,
            const float* __restrict__ w_plus, const float* __restrict__ b_plus,
            const float* __restrict__ w_prod, const float* __restrict__ b_prod,
            float* __restrict__ out, int nGroups)
{
    extern __shared__ char smraw[];
    float*  buf   = (float*) smraw;                      // [GR][3*M]
    short4* sIdx  = (short4*)(smraw + SIDX_OFF);
    float4* sWt   = (float4*)(smraw + SWT_OFF);
    float2* wepi  = (float2*)(smraw + WEPI_OFF);
    short*  eoffs = (short*) (smraw + EOFF_OFF);

    // setup scratch overlaid on buf (released before staging rows)
    short4* sP   = (short4*)smraw;                       // [M] raw parents
    int*    lvl  = (int*)(smraw + 8192);
    int*    cnt  = (int*)(smraw + 12288);
    int*    cur  = (int*)(smraw + 16384);
    int*    posA = (int*)(smraw + 20480);
    int*    offs = (int*)(smraw + 24576);                // [M+2] level offsets

    int tid  = threadIdx.x;
    int lane = tid & 31;
    int wid  = tid >> 5;

    // ---- Phase 0: stage parents, zero counters ----------------------------
    for (int i = tid; i < MDIM; i += TPB) {
        short4 p;
        p.x = (short)raw[2*i];          p.y = (short)raw[2*i + 1];
        p.z = (short)raw[2*MDIM + 2*i]; p.w = (short)raw[2*MDIM + 2*i + 1];
        sP[i] = p;
        cnt[i] = 0;
    }
    __syncthreads();

    // ---- Phase 1: exact DAG levels, warp 0 over 32-step chunks ------------
    if (wid == 0) {
        for (int c = 0; c < MDIM/32; c++) {
            int idx  = c*32 + lane;
            int base = c*32;
            short4 p = sP[idx];
            int l = 0;
            int e0 = -1, e1 = -1, e2 = -1, e3 = -1;
            int q;
            q = p.x; if (q >= MDIM) { int pc = q & (MDIM-1); if (pc < base) l = max(l, lvl[pc]+1); else e0 = pc - base; }
            q = p.y; if (q >= MDIM) { int pc = q & (MDIM-1); if (pc < base) l = max(l, lvl[pc]+1); else e1 = pc - base; }
            q = p.z; if (q >= MDIM) { int pc = q & (MDIM-1); if (pc < base) l = max(l, lvl[pc]+1); else e2 = pc - base; }
            q = p.w; if (q >= MDIM) { int pc = q & (MDIM-1); if (pc < base) l = max(l, lvl[pc]+1); else e3 = pc - base; }
            for (;;) {
                int v0 = __shfl_sync(0xffffffffu, l, e0 < 0 ? 0 : e0);
                int v1 = __shfl_sync(0xffffffffu, l, e1 < 0 ? 0 : e1);
                int v2 = __shfl_sync(0xffffffffu, l, e2 < 0 ? 0 : e2);
                int v3 = __shfl_sync(0xffffffffu, l, e3 < 0 ? 0 : e3);
                int nl = l;
                if (e0 >= 0) nl = max(nl, v0 + 1);
                if (e1 >= 0) nl = max(nl, v1 + 1);
                if (e2 >= 0) nl = max(nl, v2 + 1);
                if (e3 >= 0) nl = max(nl, v3 + 1);
                unsigned ch = __ballot_sync(0xffffffffu, nl != l);
                l = nl;
                if (!ch) break;
            }
            lvl[idx] = l;
        }
    }
    __syncthreads();

    // ---- Phase 2: level histogram -----------------------------------------
    for (int i = tid; i < MDIM; i += TPB) atomicAdd(&cnt[lvl[i]], 1);
    __syncthreads();

    // ---- Phase 3: warp-0 scan -> level offsets ----------------------------
    if (wid == 0) {
        int carry = 0;
        for (int b = 0; b < MDIM; b += 32) {
            int v = cnt[b + lane];
            int s = v;
            #pragma unroll
            for (int o = 1; o < 32; o <<= 1) {
                int t = __shfl_up_sync(0xffffffffu, s, o);
                if (lane >= o) s += t;
            }
            int excl = carry + s - v;
            offs[b + lane] = excl;
            cur[b + lane]  = excl;
            carry += __shfl_sync(0xffffffffu, s, 31);
        }
        if (lane == 0) { offs[MDIM] = MDIM; offs[MDIM+1] = MDIM; }
    }
    __syncthreads();

    // ---- Phase 4: schedule position of every step (block-local perm) ------
    for (int i = tid; i < MDIM; i += TPB) posA[i] = atomicAdd(&cur[lvl[i]], 1);
    __syncthreads();

    // ---- Phase 5: emit remapped packed schedule (ALL in this block's smem) -
    // enc: x-parent c -> c ; plus(s) -> M + 2*pos[s] ; prod(s) -> M + 2*pos[s]+1
    const float NL2E = -1.4426950408889634f;
    for (int i = tid; i < MDIM; i += TPB) {
        short4 p = sP[i];
        int pos = posA[i];
        short4 v;
        int q;
        q = p.x; v.x = (short)(q < MDIM ? q : (q < 2*MDIM ? MDIM + 2*posA[q - MDIM] : MDIM + 2*posA[q - 2*MDIM] + 1));
        q = p.y; v.y = (short)(q < MDIM ? q : (q < 2*MDIM ? MDIM + 2*posA[q - MDIM] : MDIM + 2*posA[q - 2*MDIM] + 1));
        q = p.z; v.z = (short)(q < MDIM ? q : (q < 2*MDIM ? MDIM + 2*posA[q - MDIM] : MDIM + 2*posA[q - 2*MDIM] + 1));
        q = p.w; v.w = (short)(q < MDIM ? q : (q < 2*MDIM ? MDIM + 2*posA[q - MDIM] : MDIM + 2*posA[q - 2*MDIM] + 1));
        sIdx[pos] = v;
        float4 w;
        w.x = W_sig[2*i] * NL2E; w.y = W_sig[2*i + 1] * NL2E; w.z = b_sig[i] * NL2E; w.w = 0.f;
        sWt[pos] = w;
        wepi[pos] = make_float2(w_plus[i], w_prod[i]);   // block-consistent
    }
    __syncthreads();

    // ---- Phase 6: split levels into epochs of width <= 32 -----------------
    if (tid == 0) {
        int e = 0;
        for (int L = 0; offs[L] < MDIM; L++) {
            int a = offs[L], b2 = offs[L + 1];
            while (a < b2) { eoffs[e++] = (short)a; a += 32; }
        }
        eoffs[e] = MDIM; eoffs[e+1] = MDIM; eoffs[e+2] = MDIM;
    }
    __syncthreads();                     // last block-wide barrier

    // ---- Main: one warp per row, persistent over groups -------------------
    char*  rbC = (char*)(buf + wid * ROWSTRIDE);     // row buffer base (bytes)
    float* rb  = (float*)rbC;
    char*  ppC = rbC + 4*MDIM;                       // interleaved (plus,prod)
    float bias = b_base[0] + b_plus[0] + b_prod[0];

    for (int grp = blockIdx.x; grp < nGroups; grp += gridDim.x) {
        int row = grp * GR + wid;

        // stage x (coalesced float4), fold x . W_base on the fly
        const float4* xr  = (const float4*)(x + (size_t)row * MDIM);
        const float4* wb4 = (const float4*)W_base;
        float acc = 0.f;
        #pragma unroll
        for (int k = 0; k < MDIM/128; k++) {
            float4 a  = xr[lane + 32*k];
            float4 wv = wb4[lane + 32*k];
            ((float4*)rb)[lane + 32*k] = a;
            acc = fmaf(a.x, wv.x, fmaf(a.y, wv.y, fmaf(a.z, wv.z, fmaf(a.w, wv.w, acc))));
        }
        __syncwarp();

        // epoch loop: width <= 32 guaranteed -> straight-line body; next
        // epoch's records prefetched and converted to final addresses
        // before the syncwarp (off the dependent chain).
        int s0 = 0;
        int s1 = (int)eoffs[1];
        int e  = 0;
        const char *ax, *ay, *az, *aw; char* st;
        float w0, w1, wz;
        if (lane < s1) {
            short4 q  = sIdx[lane];
            float4 ww = sWt[lane];
            ax = rbC + 4*(int)q.x; ay = rbC + 4*(int)q.y;
            az = rbC + 4*(int)q.z; aw = rbC + 4*(int)q.w;
            st = ppC + 8*lane;
            w0 = ww.x; w1 = ww.y; wz = ww.z;
        }

        while (s0 < MDIM) {
            int s2 = (int)eoffs[e + 2];
            if (lane < s1 - s0) {                 // straight-line body
                float a0 = *(const float*)ax, a1 = *(const float*)ay;
                float b0 = *(const float*)az, b1 = *(const float*)aw;
                float t  = fmaf(w0, a0, fmaf(w1, a1, wz));
                float2 o2; o2.x = sigmoid_fold(t); o2.y = b0 * b1;
                *(float2*)st = o2;                // single STS.64, contiguous
            }
            {   // prefetch next epoch (off the dependent chain)
                int sp = s1 + lane;
                if (sp < s2) {
                    short4 q  = sIdx[sp];
                    float4 ww = sWt[sp];
                    ax = rbC + 4*(int)q.x; ay = rbC + 4*(int)q.y;
                    az = rbC + 4*(int)q.z; aw = rbC + 4*(int)q.w;
                    st = ppC + 8*sp;
                    w0 = ww.x; w1 = ww.y; wz = ww.z;
                }
            }
            __syncwarp();
            s0 = s1; s1 = s2; e++;
        }

        // epilogue: interleaved pp x permuted weights, both smem
        float2* pp = (float2*)ppC;
        for (int m = lane; m < MDIM; m += 32) {
            float2 pv = pp[m];
            float2 we = wepi[m];
            acc = fmaf(pv.x, we.x, fmaf(pv.y, we.y, acc));
        }
        #pragma unroll
        for (int o = 16; o; o >>= 1) acc += __shfl_xor_sync(0xffffffffu, acc, o);
        if (lane == 0) out[row] = acc + bias;
        __syncwarp();
    }
}

// ---------------------------------------------------------------------------
extern "C" void kernel_launch(void* const* d_in, const int* in_sizes, int n_in,
                              void* d_out, int out_size) {
    const float* x  = (const float*)d_in[0];
    const int*   ri = (const int*)  d_in[1];
    const float* Wb = (const float*)d_in[2];
    const float* bb = (const float*)d_in[3];
    const float* Ws = (const float*)d_in[4];
    const float* bs = (const float*)d_in[5];
    const float* wp = (const float*)d_in[6];
    const float* bp = (const float*)d_in[7];
    const float* wq = (const float*)d_in[8];
    const float* bq = (const float*)d_in[9];
    float* out = (float*)d_out;

    int B = in_sizes[0] / MDIM;          // 8192
    int nGroups = B / GR;                // 512

    static int sm_count = 0;
    if (sm_count == 0) {
        int dev = 0;
        cudaGetDevice(&dev);
        cudaDeviceGetAttribute(&sm_count, cudaDevAttrMultiProcessorCount, dev);
        if (sm_count <= 0) sm_count = 148;
        cudaFuncSetAttribute(tree_kernel,
                             cudaFuncAttributeMaxDynamicSharedMemorySize, SMEM_BYTES);
    }
    int grid = nGroups < sm_count ? nGroups : sm_count;

    tree_kernel<<<grid, TPB, SMEM_BYTES>>>(x, ri, Wb, bb, Ws, bs, wp, bp, wq, bq,
                                           out, nGroups);
}

// round 9
// speedup vs baseline: 1.0349x; 1.0349x over previous
#include <cuda_runtime.h>

#define MDIM 1024
#define GR   16                 // rows per block = warps per block
#define TPB  512
#define ROWSTRIDE (3*MDIM)      // [x | plus | prod], separate full-bank regions

// persistent shared layout
#define BUF_BYTES  (GR*ROWSTRIDE*4)            // 196608
#define SIDX_OFF   (BUF_BYTES)                 // short4[M] remapped parents     8192
#define SW2_OFF    (SIDX_OFF + MDIM*8)         // float2[M] (w0',w1')            8192
#define SB_OFF     (SW2_OFF  + MDIM*8)         // float[M]  (b')                 4096
#define WEPI_OFF   (SB_OFF   + MDIM*4)         // float2[M] (wp',wq') permuted   8192
#define OFFS_OFF   (WEPI_OFF + MDIM*8)         // short[1026] level offsets      2056
#define SMEM_BYTES (OFFS_OFF + 2056)           // 227336 <= 232448 cap

__device__ __forceinline__ float sigmoid_fold(float t) {   // t = -z*log2e
    float e, p;
    asm("ex2.approx.f32 %0, %1;" : "=f"(e) : "f"(t));
    asm("rcp.approx.f32 %0, %1;" : "=f"(p) : "f"(1.0f + e));
    return p;
}

// ---------------------------------------------------------------------------
// Fused kernel. Setup: level-sort the 1024-step DAG, remap step ids to
// schedule order so stores are contiguous; plus and prod live in SEPARATE
// regions (full 32-bank spread for gathers):
//   enc(x,c) = c ; enc(plus,s) = M + pos[s] ; enc(prod,s) = 2M + pos[s]
// Weight tables split (float2 + float) to shrink prefetch wavefronts.
// Main: one warp per row, zero block-wide barriers, per-level __syncwarp,
// next level's records prefetched + unpacked before the sync.
// ---------------------------------------------------------------------------
__global__ void __launch_bounds__(TPB, 1)
tree_kernel(const float* __restrict__ x,      const int* __restrict__ raw,
            const float* __restrict__ W_base, const float* __restrict__ b_base,
            const float* __restrict__ W_sig,  const float* __restrict__ b_sig,
            const float* __restrict__ w_plus, const float* __restrict__ b_plus,
            const float* __restrict__ w_prod, const float* __restrict__ b_prod,
            float* __restrict__ out, int nGroups)
{
    extern __shared__ char smraw[];
    float*  buf  = (float*) smraw;                       // [GR][3*M]
    short4* sIdx = (short4*)(smraw + SIDX_OFF);
    float2* sW2  = (float2*)(smraw + SW2_OFF);
    float*  sB   = (float*) (smraw + SB_OFF);
    float2* wepi = (float2*)(smraw + WEPI_OFF);
    short*  offs = (short*) (smraw + OFFS_OFF);

    // setup scratch overlaid on buf (released before staging rows)
    short4* sP   = (short4*)smraw;                       // [M] raw parents
    int*    lvl  = (int*)(smraw + 8192);
    int*    cnt  = (int*)(smraw + 12288);
    int*    cur  = (int*)(smraw + 16384);
    int*    posA = (int*)(smraw + 20480);

    int tid  = threadIdx.x;
    int lane = tid & 31;
    int wid  = tid >> 5;

    // ---- Phase 0: stage parents, zero counters ----------------------------
    for (int i = tid; i < MDIM; i += TPB) {
        short4 p;
        p.x = (short)raw[2*i];          p.y = (short)raw[2*i + 1];
        p.z = (short)raw[2*MDIM + 2*i]; p.w = (short)raw[2*MDIM + 2*i + 1];
        sP[i] = p;
        cnt[i] = 0;
    }
    __syncthreads();

    // ---- Phase 1: exact DAG levels, warp 0 over 32-step chunks ------------
    if (wid == 0) {
        for (int c = 0; c < MDIM/32; c++) {
            int idx  = c*32 + lane;
            int base = c*32;
            short4 p = sP[idx];
            int l = 0;
            int e0 = -1, e1 = -1, e2 = -1, e3 = -1;
            int q;
            q = p.x; if (q >= MDIM) { int pc = q & (MDIM-1); if (pc < base) l = max(l, lvl[pc]+1); else e0 = pc - base; }
            q = p.y; if (q >= MDIM) { int pc = q & (MDIM-1); if (pc < base) l = max(l, lvl[pc]+1); else e1 = pc - base; }
            q = p.z; if (q >= MDIM) { int pc = q & (MDIM-1); if (pc < base) l = max(l, lvl[pc]+1); else e2 = pc - base; }
            q = p.w; if (q >= MDIM) { int pc = q & (MDIM-1); if (pc < base) l = max(l, lvl[pc]+1); else e3 = pc - base; }
            for (;;) {
                int v0 = __shfl_sync(0xffffffffu, l, e0 < 0 ? 0 : e0);
                int v1 = __shfl_sync(0xffffffffu, l, e1 < 0 ? 0 : e1);
                int v2 = __shfl_sync(0xffffffffu, l, e2 < 0 ? 0 : e2);
                int v3 = __shfl_sync(0xffffffffu, l, e3 < 0 ? 0 : e3);
                int nl = l;
                if (e0 >= 0) nl = max(nl, v0 + 1);
                if (e1 >= 0) nl = max(nl, v1 + 1);
                if (e2 >= 0) nl = max(nl, v2 + 1);
                if (e3 >= 0) nl = max(nl, v3 + 1);
                unsigned ch = __ballot_sync(0xffffffffu, nl != l);
                l = nl;
                if (!ch) break;
            }
            lvl[idx] = l;
        }
    }
    __syncthreads();

    // ---- Phase 2: level histogram -----------------------------------------
    for (int i = tid; i < MDIM; i += TPB) atomicAdd(&cnt[lvl[i]], 1);
    __syncthreads();

    // ---- Phase 3: warp-0 scan -> level offsets ----------------------------
    if (wid == 0) {
        int carry = 0;
        for (int b = 0; b < MDIM; b += 32) {
            int v = cnt[b + lane];
            int s = v;
            #pragma unroll
            for (int o = 1; o < 32; o <<= 1) {
                int t = __shfl_up_sync(0xffffffffu, s, o);
                if (lane >= o) s += t;
            }
            int excl = carry + s - v;
            offs[b + lane] = (short)excl;
            cur[b + lane]  = excl;
            carry += __shfl_sync(0xffffffffu, s, 31);
        }
        if (lane == 0) { offs[MDIM] = MDIM; offs[MDIM+1] = MDIM; }
    }
    __syncthreads();

    // ---- Phase 4: schedule position of every step (block-local perm) ------
    for (int i = tid; i < MDIM; i += TPB) posA[i] = atomicAdd(&cur[lvl[i]], 1);
    __syncthreads();

    // ---- Phase 5: emit remapped packed schedule (all block-local smem) ----
    // enc: x-parent c -> c ; plus(s) -> M + pos[s] ; prod(s) -> 2M + pos[s]
    const float NL2E = -1.4426950408889634f;
    for (int i = tid; i < MDIM; i += TPB) {
        short4 p = sP[i];
        int pos = posA[i];
        short4 v;
        int q;
        q = p.x; v.x = (short)(q < MDIM ? q : (q < 2*MDIM ? MDIM + posA[q - MDIM] : 2*MDIM + posA[q - 2*MDIM]));
        q = p.y; v.y = (short)(q < MDIM ? q : (q < 2*MDIM ? MDIM + posA[q - MDIM] : 2*MDIM + posA[q - 2*MDIM]));
        q = p.z; v.z = (short)(q < MDIM ? q : (q < 2*MDIM ? MDIM + posA[q - MDIM] : 2*MDIM + posA[q - 2*MDIM]));
        q = p.w; v.w = (short)(q < MDIM ? q : (q < 2*MDIM ? MDIM + posA[q - MDIM] : 2*MDIM + posA[q - 2*MDIM]));
        sIdx[pos] = v;
        sW2[pos]  = make_float2(W_sig[2*i] * NL2E, W_sig[2*i + 1] * NL2E);
        sB[pos]   = b_sig[i] * NL2E;
        wepi[pos] = make_float2(w_plus[i], w_prod[i]);   // block-consistent
    }
    __syncthreads();                     // last block-wide barrier

    // ---- Main: one warp per row, persistent over groups -------------------
    float* rb = buf + wid * ROWSTRIDE;           // x[0,M) plus[M,2M) prod[2M,3M)
    float bias = b_base[0] + b_plus[0] + b_prod[0];

    for (int grp = blockIdx.x; grp < nGroups; grp += gridDim.x) {
        int row = grp * GR + wid;

        // stage x (coalesced float4), fold x . W_base on the fly
        const float4* xr  = (const float4*)(x + (size_t)row * MDIM);
        const float4* wb4 = (const float4*)W_base;
        float acc = 0.f;
        #pragma unroll
        for (int k = 0; k < MDIM/128; k++) {
            float4 a  = xr[lane + 32*k];
            float4 wv = wb4[lane + 32*k];
            ((float4*)rb)[lane + 32*k] = a;
            acc = fmaf(a.x, wv.x, fmaf(a.y, wv.y, fmaf(a.z, wv.z, fmaf(a.w, wv.w, acc))));
        }
        __syncwarp();

        // level loop: contiguous stores; next level's schedule prefetched
        // and unpacked to int registers before the syncwarp.
        int s0 = 0;
        int s1 = (int)offs[1];
        int ix, iy, iz, iw; float w0, w1, wz;
        if (lane < s1) {
            short4 q = sIdx[lane]; float2 ww = sW2[lane];
            ix = q.x; iy = q.y; iz = q.z; iw = q.w;
            w0 = ww.x; w1 = ww.y; wz = sB[lane];
        }

        for (int L = 0; s0 < MDIM; L++) {
            int s2 = (int)offs[L + 2];
            int n = s1 - s0;
            if (lane < n) {                       // chunk 0 (prefetched)
                float a0 = rb[ix], a1 = rb[iy];
                float b0 = rb[iz], b1 = rb[iw];
                float t  = fmaf(w0, a0, fmaf(w1, a1, wz));
                rb[2*MDIM + s0 + lane] = b0 * b1;          // prod (contiguous)
                rb[MDIM   + s0 + lane] = sigmoid_fold(t);  // plus (contiguous)
            }
            for (int cb = s0 + 32; cb < s1; cb += 32) {    // rare wide levels
                int sp = cb + lane;
                if (sp < s1) {
                    short4 q2 = sIdx[sp]; float2 w2 = sW2[sp];
                    float a0 = rb[q2.x], a1 = rb[q2.y];
                    float b0 = rb[q2.z], b1 = rb[q2.w];
                    float t  = fmaf(w2.x, a0, fmaf(w2.y, a1, sB[sp]));
                    rb[2*MDIM + sp] = b0 * b1;
                    rb[MDIM   + sp] = sigmoid_fold(t);
                }
            }
            {   // prefetch + unpack next level chunk 0 (pre-sync, off chain)
                int sp = s1 + lane;
                if (sp < s2) {
                    short4 q = sIdx[sp]; float2 ww = sW2[sp];
                    ix = q.x; iy = q.y; iz = q.z; iw = q.w;
                    w0 = ww.x; w1 = ww.y; wz = sB[sp];
                }
            }
            __syncwarp();
            s0 = s1; s1 = s2;
        }

        // epilogue: two stride-32 conflict-free streams x permuted weights
        for (int m = lane; m < MDIM; m += 32) {
            float2 we = wepi[m];
            acc = fmaf(rb[MDIM + m], we.x, fmaf(rb[2*MDIM + m], we.y, acc));
        }
        #pragma unroll
        for (int o = 16; o; o >>= 1) acc += __shfl_xor_sync(0xffffffffu, acc, o);
        if (lane == 0) out[row] = acc + bias;
        __syncwarp();
    }
}

// ---------------------------------------------------------------------------
extern "C" void kernel_launch(void* const* d_in, const int* in_sizes, int n_in,
                              void* d_out, int out_size) {
    const float* x  = (const float*)d_in[0];
    const int*   ri = (const int*)  d_in[1];
    const float* Wb = (const float*)d_in[2];
    const float* bb = (const float*)d_in[3];
    const float* Ws = (const float*)d_in[4];
    const float* bs = (const float*)d_in[5];
    const float* wp = (const float*)d_in[6];
    const float* bp = (const float*)d_in[7];
    const float* wq = (const float*)d_in[8];
    const float* bq = (const float*)d_in[9];
    float* out = (float*)d_out;

    int B = in_sizes[0] / MDIM;          // 8192
    int nGroups = B / GR;                // 512

    static int sm_count = 0;
    if (sm_count == 0) {
        int dev = 0;
        cudaGetDevice(&dev);
        cudaDeviceGetAttribute(&sm_count, cudaDevAttrMultiProcessorCount, dev);
        if (sm_count <= 0) sm_count = 148;
        cudaFuncSetAttribute(tree_kernel,
                             cudaFuncAttributeMaxDynamicSharedMemorySize, SMEM_BYTES);
    }
    int grid = nGroups < sm_count ? nGroups : sm_count;

    tree_kernel<<<grid, TPB, SMEM_BYTES>>>(x, ri, Wb, bb, Ws, bs, wp, bp, wq, bq,
                                           out, nGroups);
}

// round 10
// speedup vs baseline: 1.3702x; 1.3239x over previous
#include <cuda_runtime.h>
#include <cuda_fp16.h>

#define MDIM 1024
#define GR   32                 // rows per block = 16 warps x 2 rows (half2-packed)
#define TPB  512
#define PAIRSTRIDE (3*MDIM)     // half2 units per pair buffer: [x | plus | prod]

// persistent shared layout (pair buffers are half2: 12KB per pair, 16 pairs)
#define BUF_BYTES  (16*PAIRSTRIDE*4)           // 196608
#define SIDX_OFF   (BUF_BYTES)                 // short4[M] remapped parents     8192
#define SW2_OFF    (SIDX_OFF + MDIM*8)         // float2[M] (w0',w1')            8192
#define SB_OFF     (SW2_OFF  + MDIM*8)         // float[M]  (b')                 4096
#define WEPI_OFF   (SB_OFF   + MDIM*4)         // float2[M] (wp',wq') permuted   8192
#define OFFS_OFF   (WEPI_OFF + MDIM*8)         // short[1026] level offsets      2056
#define SMEM_BYTES (OFFS_OFF + 2056)           // 227336 <= 232448 cap

__device__ __forceinline__ float sigmoid_fold(float t) {   // t = -z*log2e
    float e, p;
    asm("ex2.approx.f32 %0, %1;" : "=f"(e) : "f"(t));
    asm("rcp.approx.f32 %0, %1;" : "=f"(p) : "f"(1.0f + e));
    return p;
}

// ---------------------------------------------------------------------------
// Fused kernel, fp16x2 dual-row carry. Each warp owns a PAIR of rows packed
// into the two halves of a half2 buffer: pb[v] = (rowA value v, rowB value v).
// One LDS.32 gather / one STS.32 store serves BOTH rows; schedule traffic is
// shared. 32 rows per block -> 256 groups -> 2 group-waves (was 4). Compute
// is fp32 (unpack -> fma/ex2/rcp -> round-to-nearest pack); only storage is
// fp16. x.W_base is accumulated from the original fp32 global x.
// Setup (levels, counting sort, remap) identical to R9, block-local.
//   enc(x,c) = c ; enc(plus,s) = M + pos[s] ; enc(prod,s) = 2M + pos[s]
// ---------------------------------------------------------------------------
__global__ void __launch_bounds__(TPB, 1)
tree_kernel(const float* __restrict__ x,      const int* __restrict__ raw,
            const float* __restrict__ W_base, const float* __restrict__ b_base,
            const float* __restrict__ W_sig,  const float* __restrict__ b_sig,
            const float* __restrict__ w_plus, const float* __restrict__ b_plus,
            const float* __restrict__ w_prod, const float* __restrict__ b_prod,
            float* __restrict__ out, int nGroups)
{
    extern __shared__ char smraw[];
    __half2* buf  = (__half2*)smraw;                     // [16][PAIRSTRIDE]
    short4*  sIdx = (short4*)(smraw + SIDX_OFF);
    float2*  sW2  = (float2*)(smraw + SW2_OFF);
    float*   sB   = (float*) (smraw + SB_OFF);
    float2*  wepi = (float2*)(smraw + WEPI_OFF);
    short*   offs = (short*) (smraw + OFFS_OFF);

    // setup scratch overlaid on buf (released before staging rows)
    short4* sP   = (short4*)smraw;                       // [M] raw parents
    int*    lvl  = (int*)(smraw + 8192);
    int*    cnt  = (int*)(smraw + 12288);
    int*    cur  = (int*)(smraw + 16384);
    int*    posA = (int*)(smraw + 20480);

    int tid  = threadIdx.x;
    int lane = tid & 31;
    int wid  = tid >> 5;

    // ---- Phase 0: stage parents, zero counters ----------------------------
    for (int i = tid; i < MDIM; i += TPB) {
        short4 p;
        p.x = (short)raw[2*i];          p.y = (short)raw[2*i + 1];
        p.z = (short)raw[2*MDIM + 2*i]; p.w = (short)raw[2*MDIM + 2*i + 1];
        sP[i] = p;
        cnt[i] = 0;
    }
    __syncthreads();

    // ---- Phase 1: exact DAG levels, warp 0 over 32-step chunks ------------
    if (wid == 0) {
        for (int c = 0; c < MDIM/32; c++) {
            int idx  = c*32 + lane;
            int base = c*32;
            short4 p = sP[idx];
            int l = 0;
            int e0 = -1, e1 = -1, e2 = -1, e3 = -1;
            int q;
            q = p.x; if (q >= MDIM) { int pc = q & (MDIM-1); if (pc < base) l = max(l, lvl[pc]+1); else e0 = pc - base; }
            q = p.y; if (q >= MDIM) { int pc = q & (MDIM-1); if (pc < base) l = max(l, lvl[pc]+1); else e1 = pc - base; }
            q = p.z; if (q >= MDIM) { int pc = q & (MDIM-1); if (pc < base) l = max(l, lvl[pc]+1); else e2 = pc - base; }
            q = p.w; if (q >= MDIM) { int pc = q & (MDIM-1); if (pc < base) l = max(l, lvl[pc]+1); else e3 = pc - base; }
            for (;;) {
                int v0 = __shfl_sync(0xffffffffu, l, e0 < 0 ? 0 : e0);
                int v1 = __shfl_sync(0xffffffffu, l, e1 < 0 ? 0 : e1);
                int v2 = __shfl_sync(0xffffffffu, l, e2 < 0 ? 0 : e2);
                int v3 = __shfl_sync(0xffffffffu, l, e3 < 0 ? 0 : e3);
                int nl = l;
                if (e0 >= 0) nl = max(nl, v0 + 1);
                if (e1 >= 0) nl = max(nl, v1 + 1);
                if (e2 >= 0) nl = max(nl, v2 + 1);
                if (e3 >= 0) nl = max(nl, v3 + 1);
                unsigned ch = __ballot_sync(0xffffffffu, nl != l);
                l = nl;
                if (!ch) break;
            }
            lvl[idx] = l;
        }
    }
    __syncthreads();

    // ---- Phase 2: level histogram -----------------------------------------
    for (int i = tid; i < MDIM; i += TPB) atomicAdd(&cnt[lvl[i]], 1);
    __syncthreads();

    // ---- Phase 3: warp-0 scan -> level offsets ----------------------------
    if (wid == 0) {
        int carry = 0;
        for (int b = 0; b < MDIM; b += 32) {
            int v = cnt[b + lane];
            int s = v;
            #pragma unroll
            for (int o = 1; o < 32; o <<= 1) {
                int t = __shfl_up_sync(0xffffffffu, s, o);
                if (lane >= o) s += t;
            }
            int excl = carry + s - v;
            offs[b + lane] = (short)excl;
            cur[b + lane]  = excl;
            carry += __shfl_sync(0xffffffffu, s, 31);
        }
        if (lane == 0) { offs[MDIM] = MDIM; offs[MDIM+1] = MDIM; }
    }
    __syncthreads();

    // ---- Phase 4: schedule position of every step (block-local perm) ------
    for (int i = tid; i < MDIM; i += TPB) posA[i] = atomicAdd(&cur[lvl[i]], 1);
    __syncthreads();

    // ---- Phase 5: emit remapped packed schedule (all block-local smem) ----
    const float NL2E = -1.4426950408889634f;
    for (int i = tid; i < MDIM; i += TPB) {
        short4 p = sP[i];
        int pos = posA[i];
        short4 v;
        int q;
        q = p.x; v.x = (short)(q < MDIM ? q : (q < 2*MDIM ? MDIM + posA[q - MDIM] : 2*MDIM + posA[q - 2*MDIM]));
        q = p.y; v.y = (short)(q < MDIM ? q : (q < 2*MDIM ? MDIM + posA[q - MDIM] : 2*MDIM + posA[q - 2*MDIM]));
        q = p.z; v.z = (short)(q < MDIM ? q : (q < 2*MDIM ? MDIM + posA[q - MDIM] : 2*MDIM + posA[q - 2*MDIM]));
        q = p.w; v.w = (short)(q < MDIM ? q : (q < 2*MDIM ? MDIM + posA[q - MDIM] : 2*MDIM + posA[q - 2*MDIM]));
        sIdx[pos] = v;
        sW2[pos]  = make_float2(W_sig[2*i] * NL2E, W_sig[2*i + 1] * NL2E);
        sB[pos]   = b_sig[i] * NL2E;
        wepi[pos] = make_float2(w_plus[i], w_prod[i]);   // block-consistent
    }
    __syncthreads();                     // last block-wide barrier

    // ---- Main: one warp per ROW-PAIR, persistent over groups --------------
    __half2* pb = buf + wid * PAIRSTRIDE;    // x[0,M) plus[M,2M) prod[2M,3M)
    float bias = b_base[0] + b_plus[0] + b_prod[0];

    for (int grp = blockIdx.x; grp < nGroups; grp += gridDim.x) {
        int rowA = grp * GR + 2*wid;

        // stage both rows (fp32 coalesced), pack half2, fold x.W_base in fp32
        const float4* xrA = (const float4*)(x + (size_t)rowA * MDIM);
        const float4* xrB = (const float4*)(x + (size_t)(rowA + 1) * MDIM);
        const float4* wb4 = (const float4*)W_base;
        float accA = 0.f, accB = 0.f;
        #pragma unroll
        for (int k = 0; k < MDIM/128; k++) {
            float4 a  = xrA[lane + 32*k];
            float4 b  = xrB[lane + 32*k];
            float4 wv = wb4[lane + 32*k];
            __half2 h[4];
            h[0] = __floats2half2_rn(a.x, b.x);
            h[1] = __floats2half2_rn(a.y, b.y);
            h[2] = __floats2half2_rn(a.z, b.z);
            h[3] = __floats2half2_rn(a.w, b.w);
            ((uint4*)pb)[lane + 32*k] = *(const uint4*)h;
            accA = fmaf(a.x, wv.x, fmaf(a.y, wv.y, fmaf(a.z, wv.z, fmaf(a.w, wv.w, accA))));
            accB = fmaf(b.x, wv.x, fmaf(b.y, wv.y, fmaf(b.z, wv.z, fmaf(b.w, wv.w, accB))));
        }
        __syncwarp();

        // level loop: one LDS.32 per gather serves both rows; contiguous
        // STS.32 stores; next level's schedule prefetched + unpacked pre-sync
        int s0 = 0;
        int s1 = (int)offs[1];
        int ix, iy, iz, iw; float w0, w1, wz;
        if (lane < s1) {
            short4 q = sIdx[lane]; float2 ww = sW2[lane];
            ix = q.x; iy = q.y; iz = q.z; iw = q.w;
            w0 = ww.x; w1 = ww.y; wz = sB[lane];
        }

        for (int L = 0; s0 < MDIM; L++) {
            int s2 = (int)offs[L + 2];
            int n = s1 - s0;
            if (lane < n) {                       // chunk 0 (prefetched)
                float2 a0 = __half22float2(pb[ix]);
                float2 a1 = __half22float2(pb[iy]);
                float2 b0 = __half22float2(pb[iz]);
                float2 b1 = __half22float2(pb[iw]);
                float tA = fmaf(w0, a0.x, fmaf(w1, a1.x, wz));
                float tB = fmaf(w0, a0.y, fmaf(w1, a1.y, wz));
                pb[2*MDIM + s0 + lane] = __floats2half2_rn(b0.x*b1.x, b0.y*b1.y);
                pb[MDIM   + s0 + lane] = __floats2half2_rn(sigmoid_fold(tA), sigmoid_fold(tB));
            }
            for (int cb = s0 + 32; cb < s1; cb += 32) {    // rare wide levels
                int sp = cb + lane;
                if (sp < s1) {
                    short4 q2 = sIdx[sp]; float2 w2 = sW2[sp];
                    float2 a0 = __half22float2(pb[q2.x]);
                    float2 a1 = __half22float2(pb[q2.y]);
                    float2 b0 = __half22float2(pb[q2.z]);
                    float2 b1 = __half22float2(pb[q2.w]);
                    float tA = fmaf(w2.x, a0.x, fmaf(w2.y, a1.x, sB[sp]));
                    float tB = fmaf(w2.x, a0.y, fmaf(w2.y, a1.y, sB[sp]));
                    pb[2*MDIM + sp] = __floats2half2_rn(b0.x*b1.x, b0.y*b1.y);
                    pb[MDIM   + sp] = __floats2half2_rn(sigmoid_fold(tA), sigmoid_fold(tB));
                }
            }
            {   // prefetch + unpack next level chunk 0 (pre-sync, off chain)
                int sp = s1 + lane;
                if (sp < s2) {
                    short4 q = sIdx[sp]; float2 ww = sW2[sp];
                    ix = q.x; iy = q.y; iz = q.z; iw = q.w;
                    w0 = ww.x; w1 = ww.y; wz = sB[sp];
                }
            }
            __syncwarp();
            s0 = s1; s1 = s2;
        }

        // epilogue: both rows' plus/prod dots (stride-32, conflict-free)
        for (int m = lane; m < MDIM; m += 32) {
            float2 pl = __half22float2(pb[MDIM   + m]);
            float2 pr = __half22float2(pb[2*MDIM + m]);
            float2 we = wepi[m];
            accA = fmaf(pl.x, we.x, fmaf(pr.x, we.y, accA));
            accB = fmaf(pl.y, we.x, fmaf(pr.y, we.y, accB));
        }
        #pragma unroll
        for (int o = 16; o; o >>= 1) {
            accA += __shfl_xor_sync(0xffffffffu, accA, o);
            accB += __shfl_xor_sync(0xffffffffu, accB, o);
        }
        if (lane == 0) {
            out[rowA]     = accA + bias;
            out[rowA + 1] = accB + bias;
        }
        __syncwarp();
    }
}

// ---------------------------------------------------------------------------
extern "C" void kernel_launch(void* const* d_in, const int* in_sizes, int n_in,
                              void* d_out, int out_size) {
    const float* x  = (const float*)d_in[0];
    const int*   ri = (const int*)  d_in[1];
    const float* Wb = (const float*)d_in[2];
    const float* bb = (const float*)d_in[3];
    const float* Ws = (const float*)d_in[4];
    const float* bs = (const float*)d_in[5];
    const float* wp = (const float*)d_in[6];
    const float* bp = (const float*)d_in[7];
    const float* wq = (const float*)d_in[8];
    const float* bq = (const float*)d_in[9];
    float* out = (float*)d_out;

    int B = in_sizes[0] / MDIM;          // 8192
    int nGroups = B / GR;                // 256

    static int sm_count = 0;
    if (sm_count == 0) {
        int dev = 0;
        cudaGetDevice(&dev);
        cudaDeviceGetAttribute(&sm_count, cudaDevAttrMultiProcessorCount, dev);
        if (sm_count <= 0) sm_count = 148;
        cudaFuncSetAttribute(tree_kernel,
                             cudaFuncAttributeMaxDynamicSharedMemorySize, SMEM_BYTES);
    }
    int grid = nGroups < sm_count ? nGroups : sm_count;

    tree_kernel<<<grid, TPB, SMEM_BYTES>>>(x, ri, Wb, bb, Ws, bs, wp, bp, wq, bq,
                                           out, nGroups);
}

// round 12
// speedup vs baseline: 1.5333x; 1.1191x over previous
#include <cuda_runtime.h>
#include <cuda_fp16.h>

#define MDIM 1024
#define GR   32                 // rows per block = 16 warps x 2 rows (half2-packed)
#define TPB  512
#define PAIRSTRIDE (3*MDIM)     // half2 units per pair buffer: [x | plus | prod]

typedef unsigned int u32;

// persistent shared layout (pair buffers are half2: 12KB per pair, 16 pairs)
#define BUF_BYTES  (16*PAIRSTRIDE*4)           // 196608
#define SIDX_OFF   (BUF_BYTES)                 // short4[M] remapped parents     8192
#define SWAB_OFF   (SIDX_OFF + MDIM*8)         // uint2[M] (w0x2,w1x2) half2 bc  8192
#define SBB_OFF    (SWAB_OFF + MDIM*8)         // u32[M]   (bx2) half2 bc        4096
#define WEPI_OFF   (SBB_OFF  + MDIM*4)         // float2[M] (wp',wq') permuted   8192
#define OFFS_OFF   (WEPI_OFF + MDIM*8)         // short[1026] level offsets      2056
#define SMEM_BYTES (OFFS_OFF + 2056)           // 227336 <= 232448 cap

__device__ __forceinline__ __half2 tanh2_approx(__half2 v) {
    u32 u = *reinterpret_cast<u32*>(&v);
    u32 r;
    asm("tanh.approx.f16x2 %0, %1;" : "=r"(r) : "r"(u));
    return *reinterpret_cast<__half2*>(&r);
}

// ---------------------------------------------------------------------------
// Fused kernel, fp16x2 dual-row carry AND fp16x2 math. Each warp owns a PAIR
// of rows packed in half2: pb[v] = (rowA v, rowB v). One LDS.32 gather / one
// STS.32 serves both rows. Sigmoid via hardware tanh.approx.f16x2:
//   sigmoid(z) = 0.5*tanh(z/2)+0.5, the 1/2 folded into weights at setup.
// prod computed with HMUL2 (rounding identical to f32-mul + fp16 round).
// 32 rows/block -> 256 groups -> 2 group-waves. Setup (levels, counting
// sort, remap to schedule order, contiguous stores) as R9/R10, block-local:
//   enc(x,c) = c ; enc(plus,s) = M + pos[s] ; enc(prod,s) = 2M + pos[s]
// ---------------------------------------------------------------------------
__global__ void __launch_bounds__(TPB, 1)
tree_kernel(const float* __restrict__ x,      const int* __restrict__ raw,
            const float* __restrict__ W_base, const float* __restrict__ b_base,
            const float* __restrict__ W_sig,  const float* __restrict__ b_sig,
            const float* __restrict__ w_plus, const float* __restrict__ b_plus,
            const float* __restrict__ w_prod, const float* __restrict__ b_prod,
            float* __restrict__ out, int nGroups)
{
    extern __shared__ char smraw[];
    __half2* buf  = (__half2*)smraw;                     // [16][PAIRSTRIDE]
    short4*  sIdx = (short4*)(smraw + SIDX_OFF);
    uint2*   sWab = (uint2*) (smraw + SWAB_OFF);
    u32*     sBb  = (u32*)   (smraw + SBB_OFF);
    float2*  wepi = (float2*)(smraw + WEPI_OFF);
    short*   offs = (short*) (smraw + OFFS_OFF);

    // setup scratch overlaid on buf (released before staging rows)
    short4* sP   = (short4*)smraw;                       // [M] raw parents
    int*    lvl  = (int*)(smraw + 8192);
    int*    cnt  = (int*)(smraw + 12288);
    int*    cur  = (int*)(smraw + 16384);
    int*    posA = (int*)(smraw + 20480);

    int tid  = threadIdx.x;
    int lane = tid & 31;
    int wid  = tid >> 5;

    // ---- Phase 0: stage parents, zero counters ----------------------------
    for (int i = tid; i < MDIM; i += TPB) {
        short4 p;
        p.x = (short)raw[2*i];          p.y = (short)raw[2*i + 1];
        p.z = (short)raw[2*MDIM + 2*i]; p.w = (short)raw[2*MDIM + 2*i + 1];
        sP[i] = p;
        cnt[i] = 0;
    }
    __syncthreads();

    // ---- Phase 1: exact DAG levels, warp 0 over 32-step chunks ------------
    if (wid == 0) {
        for (int c = 0; c < MDIM/32; c++) {
            int idx  = c*32 + lane;
            int base = c*32;
            short4 p = sP[idx];
            int l = 0;
            int e0 = -1, e1 = -1, e2 = -1, e3 = -1;
            int q;
            q = p.x; if (q >= MDIM) { int pc = q & (MDIM-1); if (pc < base) l = max(l, lvl[pc]+1); else e0 = pc - base; }
            q = p.y; if (q >= MDIM) { int pc = q & (MDIM-1); if (pc < base) l = max(l, lvl[pc]+1); else e1 = pc - base; }
            q = p.z; if (q >= MDIM) { int pc = q & (MDIM-1); if (pc < base) l = max(l, lvl[pc]+1); else e2 = pc - base; }
            q = p.w; if (q >= MDIM) { int pc = q & (MDIM-1); if (pc < base) l = max(l, lvl[pc]+1); else e3 = pc - base; }
            for (;;) {
                int v0 = __shfl_sync(0xffffffffu, l, e0 < 0 ? 0 : e0);
                int v1 = __shfl_sync(0xffffffffu, l, e1 < 0 ? 0 : e1);
                int v2 = __shfl_sync(0xffffffffu, l, e2 < 0 ? 0 : e2);
                int v3 = __shfl_sync(0xffffffffu, l, e3 < 0 ? 0 : e3);
                int nl = l;
                if (e0 >= 0) nl = max(nl, v0 + 1);
                if (e1 >= 0) nl = max(nl, v1 + 1);
                if (e2 >= 0) nl = max(nl, v2 + 1);
                if (e3 >= 0) nl = max(nl, v3 + 1);
                unsigned ch = __ballot_sync(0xffffffffu, nl != l);
                l = nl;
                if (!ch) break;
            }
            lvl[idx] = l;
        }
    }
    __syncthreads();

    // ---- Phase 2: level histogram -----------------------------------------
    for (int i = tid; i < MDIM; i += TPB) atomicAdd(&cnt[lvl[i]], 1);
    __syncthreads();

    // ---- Phase 3: warp-0 scan -> level offsets ----------------------------
    if (wid == 0) {
        int carry = 0;
        for (int b = 0; b < MDIM; b += 32) {
            int v = cnt[b + lane];
            int s = v;
            #pragma unroll
            for (int o = 1; o < 32; o <<= 1) {
                int t = __shfl_up_sync(0xffffffffu, s, o);
                if (lane >= o) s += t;
            }
            int excl = carry + s - v;
            offs[b + lane] = (short)excl;
            cur[b + lane]  = excl;
            carry += __shfl_sync(0xffffffffu, s, 31);
        }
        if (lane == 0) { offs[MDIM] = MDIM; offs[MDIM+1] = MDIM; }
    }
    __syncthreads();

    // ---- Phase 4: schedule position of every step (block-local perm) ------
    for (int i = tid; i < MDIM; i += TPB) posA[i] = atomicAdd(&cur[lvl[i]], 1);
    __syncthreads();

    // ---- Phase 5: emit remapped packed schedule (all block-local smem) ----
    // sigmoid weights pre-halved (tanh identity) and broadcast to half2.
    for (int i = tid; i < MDIM; i += TPB) {
        short4 p = sP[i];
        int pos = posA[i];
        short4 v;
        int q;
        q = p.x; v.x = (short)(q < MDIM ? q : (q < 2*MDIM ? MDIM + posA[q - MDIM] : 2*MDIM + posA[q - 2*MDIM]));
        q = p.y; v.y = (short)(q < MDIM ? q : (q < 2*MDIM ? MDIM + posA[q - MDIM] : 2*MDIM + posA[q - 2*MDIM]));
        q = p.z; v.z = (short)(q < MDIM ? q : (q < 2*MDIM ? MDIM + posA[q - MDIM] : 2*MDIM + posA[q - 2*MDIM]));
        q = p.w; v.w = (short)(q < MDIM ? q : (q < 2*MDIM ? MDIM + posA[q - MDIM] : 2*MDIM + posA[q - 2*MDIM]));
        sIdx[pos] = v;
        __half2 h0 = __float2half2_rn(W_sig[2*i]     * 0.5f);
        __half2 h1 = __float2half2_rn(W_sig[2*i + 1] * 0.5f);
        __half2 hb = __float2half2_rn(b_sig[i]       * 0.5f);
        uint2 wab;
        wab.x = *reinterpret_cast<u32*>(&h0);
        wab.y = *reinterpret_cast<u32*>(&h1);
        sWab[pos] = wab;
        sBb[pos]  = *reinterpret_cast<u32*>(&hb);
        wepi[pos] = make_float2(w_plus[i], w_prod[i]);   // block-consistent
    }
    __syncthreads();                     // last block-wide barrier

    // ---- Main: one warp per ROW-PAIR, persistent over groups --------------
    __half2* pb = buf + wid * PAIRSTRIDE;    // x[0,M) plus[M,2M) prod[2M,3M)
    float bias = b_base[0] + b_plus[0] + b_prod[0];
    const __half2 H05 = __floats2half2_rn(0.5f, 0.5f);

    for (int grp = blockIdx.x; grp < nGroups; grp += gridDim.x) {
        int rowA = grp * GR + 2*wid;

        // stage both rows (fp32 coalesced), pack half2, fold x.W_base in fp32
        const float4* xrA = (const float4*)(x + (size_t)rowA * MDIM);
        const float4* xrB = (const float4*)(x + (size_t)(rowA + 1) * MDIM);
        const float4* wb4 = (const float4*)W_base;
        float accA = 0.f, accB = 0.f;
        #pragma unroll
        for (int k = 0; k < MDIM/128; k++) {
            float4 a  = xrA[lane + 32*k];
            float4 b  = xrB[lane + 32*k];
            float4 wv = wb4[lane + 32*k];
            __half2 h[4];
            h[0] = __floats2half2_rn(a.x, b.x);
            h[1] = __floats2half2_rn(a.y, b.y);
            h[2] = __floats2half2_rn(a.z, b.z);
            h[3] = __floats2half2_rn(a.w, b.w);
            ((uint4*)pb)[lane + 32*k] = *(const uint4*)h;
            accA = fmaf(a.x, wv.x, fmaf(a.y, wv.y, fmaf(a.z, wv.z, fmaf(a.w, wv.w, accA))));
            accB = fmaf(b.x, wv.x, fmaf(b.y, wv.y, fmaf(b.z, wv.z, fmaf(b.w, wv.w, accB))));
        }
        __syncwarp();

        // level loop: all math in f16x2 (both rows per instruction);
        // next level's schedule prefetched + unpacked pre-sync.
        int s0 = 0;
        int s1 = (int)offs[1];
        int ix, iy, iz, iw; __half2 w0x2, w1x2, bx2;
        if (lane < s1) {
            short4 q = sIdx[lane];
            uint2  wab = sWab[lane];
            u32    bw  = sBb[lane];
            ix = q.x; iy = q.y; iz = q.z; iw = q.w;
            w0x2 = *reinterpret_cast<__half2*>(&wab.x);
            w1x2 = *reinterpret_cast<__half2*>(&wab.y);
            bx2  = *reinterpret_cast<__half2*>(&bw);
        }

        for (int L = 0; s0 < MDIM; L++) {
            int s2 = (int)offs[L + 2];
            int n = s1 - s0;
            if (lane < n) {                       // chunk 0 (prefetched)
                __half2 a0 = pb[ix], a1 = pb[iy];
                __half2 m0 = pb[iz], m1 = pb[iw];
                __half2 z  = __hfma2(w0x2, a0, __hfma2(w1x2, a1, bx2));
                __half2 th = tanh2_approx(z);
                pb[2*MDIM + s0 + lane] = __hmul2(m0, m1);        // prod
                pb[MDIM   + s0 + lane] = __hfma2(th, H05, H05);  // plus
            }
            for (int cb = s0 + 32; cb < s1; cb += 32) {    // rare wide levels
                int sp = cb + lane;
                if (sp < s1) {
                    short4 q2 = sIdx[sp];
                    uint2  wab2 = sWab[sp];
                    u32    bw2  = sBb[sp];
                    __half2 a0 = pb[q2.x], a1 = pb[q2.y];
                    __half2 m0 = pb[q2.z], m1 = pb[q2.w];
                    __half2 z  = __hfma2(*reinterpret_cast<__half2*>(&wab2.x), a0,
                                 __hfma2(*reinterpret_cast<__half2*>(&wab2.y), a1,
                                         *reinterpret_cast<__half2*>(&bw2)));
                    __half2 th = tanh2_approx(z);
                    pb[2*MDIM + sp] = __hmul2(m0, m1);
                    pb[MDIM   + sp] = __hfma2(th, H05, H05);
                }
            }
            {   // prefetch + unpack next level chunk 0 (pre-sync, off chain)
                int sp = s1 + lane;
                if (sp < s2) {
                    short4 q = sIdx[sp];
                    uint2  wab = sWab[sp];
                    u32    bw  = sBb[sp];
                    ix = q.x; iy = q.y; iz = q.z; iw = q.w;
                    w0x2 = *reinterpret_cast<__half2*>(&wab.x);
                    w1x2 = *reinterpret_cast<__half2*>(&wab.y);
                    bx2  = *reinterpret_cast<__half2*>(&bw);
                }
            }
            __syncwarp();
            s0 = s1; s1 = s2;
        }

        // epilogue: both rows' plus/prod dots (stride-32, conflict-free)
        for (int m = lane; m < MDIM; m += 32) {
            float2 pl = __half22float2(pb[MDIM   + m]);
            float2 pr = __half22float2(pb[2*MDIM + m]);
            float2 we = wepi[m];
            accA = fmaf(pl.x, we.x, fmaf(pr.x, we.y, accA));
            accB = fmaf(pl.y, we.x, fmaf(pr.y, we.y, accB));
        }
        #pragma unroll
        for (int o = 16; o; o >>= 1) {
            accA += __shfl_xor_sync(0xffffffffu, accA, o);
            accB += __shfl_xor_sync(0xffffffffu, accB, o);
        }
        if (lane == 0) {
            out[rowA]     = accA + bias;
            out[rowA + 1] = accB + bias;
        }
        __syncwarp();
    }
}

// ---------------------------------------------------------------------------
extern "C" void kernel_launch(void* const* d_in, const int* in_sizes, int n_in,
                              void* d_out, int out_size) {
    const float* x  = (const float*)d_in[0];
    const int*   ri = (const int*)  d_in[1];
    const float* Wb = (const float*)d_in[2];
    const float* bb = (const float*)d_in[3];
    const float* Ws = (const float*)d_in[4];
    const float* bs = (const float*)d_in[5];
    const float* wp = (const float*)d_in[6];
    const float* bp = (const float*)d_in[7];
    const float* wq = (const float*)d_in[8];
    const float* bq = (const float*)d_in[9];
    float* out = (float*)d_out;

    int B = in_sizes[0] / MDIM;          // 8192
    int nGroups = B / GR;                // 256

    static int sm_count = 0;
    if (sm_count == 0) {
        int dev = 0;
        cudaGetDevice(&dev);
        cudaDeviceGetAttribute(&sm_count, cudaDevAttrMultiProcessorCount, dev);
        if (sm_count <= 0) sm_count = 148;
        cudaFuncSetAttribute(tree_kernel,
                             cudaFuncAttributeMaxDynamicSharedMemorySize, SMEM_BYTES);
    }
    int grid = nGroups < sm_count ? nGroups : sm_count;

    tree_kernel<<<grid, TPB, SMEM_BYTES>>>(x, ri, Wb, bb, Ws, bs, wp, bp, wq, bq,
                                           out, nGroups);
}